// round 1
// baseline (speedup 1.0000x reference)
#include <cuda_runtime.h>
#include <math.h>

#define NN 10000
#define NE 160000

// ---------------- device scratch (static, allocation-free) ----------------
__device__ float g_t[NN * 16];
__device__ float g_qW[NN * 8];
__device__ float g_h1k[(size_t)NE * 128];
__device__ float g_h2k[(size_t)NE * 128];
__device__ float g_h1v[(size_t)NE * 128];
__device__ float g_h2v[(size_t)NE * 128];
__device__ float g_WK[(size_t)NE * 512];
__device__ float g_WV[(size_t)NE * 1024];
__device__ float g_vbuf[(size_t)NE * 16];
__device__ float g_logit[NE];
__device__ float g_m[NN];
__device__ float g_z[NN];
__device__ float g_agg[NN * 16];
__device__ float g_colsum[64];
__device__ float g_colsumsq[64];
__device__ float g_outpre[NN * 64];

// ---------------- helpers ----------------
__device__ __forceinline__ void atomicMaxF(float* addr, float v) {
    if (v >= 0.f)
        atomicMax((int*)addr, __float_as_int(v));
    else
        atomicMin((unsigned int*)addr, __float_as_uint(v));
}

// ---------------- init ----------------
__global__ void init_kernel() {
    int i = blockIdx.x * 256 + threadIdx.x;
    if (i < NN) { g_m[i] = -INFINITY; g_z[i] = 0.f; }
    if (i < NN * 16) g_agg[i] = 0.f;
    if (i < 64) { g_colsum[i] = 0.f; g_colsumsq[i] = 0.f; }
}

// ---------------- node linears: t = nd@Wi/8 ; qW = ((t@Wq)/4)@Wd/8 ----------------
__global__ __launch_bounds__(128) void node_kernel(
    const float* __restrict__ node_data, const float* __restrict__ W_input,
    const float* __restrict__ W_query, const float* __restrict__ W_dot)
{
    __shared__ float Wi[64 * 16];
    __shared__ float Wq[16 * 8];
    __shared__ float Wd[64];
    __shared__ float tsh[8][16];
    __shared__ float qsh[8][8];
    int tid = threadIdx.x;
    for (int i = tid; i < 1024; i += 128) Wi[i] = W_input[i];
    if (tid < 128) Wq[tid] = W_query[tid];
    if (tid < 64) Wd[tid] = W_dot[tid];
    __syncthreads();

    int n_loc = tid >> 4, c = tid & 15;
    int n = blockIdx.x * 8 + n_loc;
    float tv = 0.f;
    if (n < NN) {
        const float* nd = node_data + (size_t)n * 64;
        #pragma unroll 8
        for (int i = 0; i < 64; i++) tv += nd[i] * Wi[i * 16 + c];
        tv *= 0.125f;
        g_t[n * 16 + c] = tv;
    }
    tsh[n_loc][c] = tv;
    __syncthreads();

    if (tid < 64) {
        int nl = tid >> 3, b = tid & 7;
        float qv = 0.f;
        #pragma unroll
        for (int a = 0; a < 16; a++) qv += tsh[nl][a] * Wq[a * 8 + b];
        qsh[nl][b] = qv * 0.25f;
    }
    __syncthreads();
    if (tid < 64) {
        int nl = tid >> 3, b = tid & 7;
        int n2 = blockIdx.x * 8 + nl;
        if (n2 < NN) {
            float s = 0.f;
            #pragma unroll
            for (int a = 0; a < 8; a++) s += qsh[nl][a] * Wd[a * 8 + b];
            g_qW[n2 * 8 + b] = s * 0.125f;
        }
    }
}

// ---------------- tiled SGEMM: C = act(A[M,K]@B[K,N] + bias) ----------------
// BM=BN=128, BK=32, 256 threads, 8x8 microtile. M%128==0, N%128==0, K%32==0.
template <bool RELU>
__global__ __launch_bounds__(256) void gemm_kernel(
    const float* __restrict__ A, const float* __restrict__ B,
    const float* __restrict__ bias, float* __restrict__ C,
    int M, int N, int K)
{
    __shared__ float As[32][129];
    __shared__ float Bs[32][128];
    const int tid = threadIdx.x;
    const int m0 = blockIdx.y * 128;
    const int n0 = blockIdx.x * 128;
    const int tr = tid >> 4;  // 0..15
    const int tc = tid & 15;  // 0..15

    float acc[8][8];
    #pragma unroll
    for (int i = 0; i < 8; i++)
        #pragma unroll
        for (int j = 0; j < 8; j++) acc[i][j] = 0.f;

    for (int k0 = 0; k0 < K; k0 += 32) {
        #pragma unroll
        for (int i = 0; i < 4; i++) {
            int idx = tid + i * 256;
            int row = idx >> 3;
            int q = idx & 7;
            float4 av = *(const float4*)(A + (size_t)(m0 + row) * K + k0 + q * 4);
            As[q * 4 + 0][row] = av.x;
            As[q * 4 + 1][row] = av.y;
            As[q * 4 + 2][row] = av.z;
            As[q * 4 + 3][row] = av.w;
        }
        #pragma unroll
        for (int i = 0; i < 4; i++) {
            int idx = tid + i * 256;
            int kk = idx >> 5;
            int c4 = idx & 31;
            *(float4*)(&Bs[kk][c4 * 4]) =
                *(const float4*)(B + (size_t)(k0 + kk) * N + n0 + c4 * 4);
        }
        __syncthreads();
        #pragma unroll
        for (int kk = 0; kk < 32; kk++) {
            float a[8], b[8];
            #pragma unroll
            for (int i = 0; i < 8; i++) a[i] = As[kk][tr * 8 + i];
            float4 b0 = *(float4*)(&Bs[kk][tc * 8]);
            float4 b1 = *(float4*)(&Bs[kk][tc * 8 + 4]);
            b[0] = b0.x; b[1] = b0.y; b[2] = b0.z; b[3] = b0.w;
            b[4] = b1.x; b[5] = b1.y; b[6] = b1.z; b[7] = b1.w;
            #pragma unroll
            for (int i = 0; i < 8; i++)
                #pragma unroll
                for (int j = 0; j < 8; j++)
                    acc[i][j] = fmaf(a[i], b[j], acc[i][j]);
        }
        __syncthreads();
    }

    float bb[8];
    #pragma unroll
    for (int j = 0; j < 8; j++) bb[j] = bias[n0 + tc * 8 + j];
    #pragma unroll
    for (int i = 0; i < 8; i++) {
        int row = m0 + tr * 8 + i;
        float v[8];
        #pragma unroll
        for (int j = 0; j < 8; j++) {
            float x = acc[i][j] + bb[j];
            v[j] = RELU ? fmaxf(x, 0.f) : x;
        }
        *(float4*)(C + (size_t)row * N + n0 + tc * 8) = make_float4(v[0], v[1], v[2], v[3]);
        *(float4*)(C + (size_t)row * N + n0 + tc * 8 + 4) = make_float4(v[4], v[5], v[6], v[7]);
    }
}

// ---------------- per-edge bilinear contraction + logits (warp per edge) ----------------
__global__ __launch_bounds__(256) void uv_kernel(
    const int* __restrict__ ei, const float* __restrict__ sh)
{
    int gw = (blockIdx.x * 256 + threadIdx.x) >> 5;
    int lane = threadIdx.x & 31;
    if (gw >= NE) return;
    int e = gw;
    int src = ei[e];
    int dst = ei[NE + e];

    // u[as] = t[src,a]*sh[e,s] / sqrt(64);  lane owns as = lane, lane+32
    float shl = sh[e * 4 + (lane & 3)];
    float u_lo = g_t[src * 16 + (lane >> 2)] * shl * 0.125f;
    float u_hi = g_t[src * 16 + 8 + (lane >> 2)] * shl * 0.125f;

    // k partial (C_KEY=8): wk layout [as][b], as index = a*4+s
    const float* wkp = g_WK + (size_t)e * 512;
    float4 ka0 = *(const float4*)(wkp + lane * 8);
    float4 ka1 = *(const float4*)(wkp + lane * 8 + 4);
    float4 kb0 = *(const float4*)(wkp + 256 + lane * 8);
    float4 kb1 = *(const float4*)(wkp + 256 + lane * 8 + 4);
    float kacc[8];
    kacc[0] = u_lo * ka0.x + u_hi * kb0.x;
    kacc[1] = u_lo * ka0.y + u_hi * kb0.y;
    kacc[2] = u_lo * ka0.z + u_hi * kb0.z;
    kacc[3] = u_lo * ka0.w + u_hi * kb0.w;
    kacc[4] = u_lo * ka1.x + u_hi * kb1.x;
    kacc[5] = u_lo * ka1.y + u_hi * kb1.y;
    kacc[6] = u_lo * ka1.z + u_hi * kb1.z;
    kacc[7] = u_lo * ka1.w + u_hi * kb1.w;

    // logit on partials (dot with qW is linear -> reduce one scalar, not 8)
    const float* qwp = g_qW + dst * 8;
    float lp = 0.f;
    #pragma unroll
    for (int b = 0; b < 8; b++) lp += kacc[b] * qwp[b];
    #pragma unroll
    for (int off = 16; off; off >>= 1) lp += __shfl_xor_sync(0xffffffffu, lp, off);

    // v (C_OTP=16)
    const float* wvp = g_WV + (size_t)e * 1024;
    float vacc[16];
    {
        const float* p = wvp + lane * 16;
        #pragma unroll
        for (int q = 0; q < 4; q++) {
            float4 w = *(const float4*)(p + q * 4);
            vacc[q * 4 + 0] = u_lo * w.x;
            vacc[q * 4 + 1] = u_lo * w.y;
            vacc[q * 4 + 2] = u_lo * w.z;
            vacc[q * 4 + 3] = u_lo * w.w;
        }
        p = wvp + 512 + lane * 16;
        #pragma unroll
        for (int q = 0; q < 4; q++) {
            float4 w = *(const float4*)(p + q * 4);
            vacc[q * 4 + 0] += u_hi * w.x;
            vacc[q * 4 + 1] += u_hi * w.y;
            vacc[q * 4 + 2] += u_hi * w.z;
            vacc[q * 4 + 3] += u_hi * w.w;
        }
    }
    #pragma unroll
    for (int off = 16; off; off >>= 1)
        #pragma unroll
        for (int b = 0; b < 16; b++)
            vacc[b] += __shfl_xor_sync(0xffffffffu, vacc[b], off);

    float vout = 0.f;
    #pragma unroll
    for (int b = 0; b < 16; b++) vout = (lane == b) ? vacc[b] : vout;
    if (lane < 16) g_vbuf[(size_t)e * 16 + lane] = vout;
    if (lane == 0) {
        g_logit[e] = lp;
        atomicMaxF(&g_m[dst], lp);
    }
}

// ---------------- softmax numerator + segment sums ----------------
__global__ void attn_agg_kernel(const int* __restrict__ ei)
{
    int e = blockIdx.x * 256 + threadIdx.x;
    if (e >= NE) return;
    int dst = ei[NE + e];
    float p = expf(g_logit[e] - g_m[dst]);
    atomicAdd(&g_z[dst], p);
    const float* v = g_vbuf + (size_t)e * 16;
    float* agg = g_agg + dst * 16;
    #pragma unroll
    for (int c = 0; c < 16; c++) atomicAdd(&agg[c], p * v[c]);
}

// ---------------- output linear + residual + BN stats ----------------
__global__ __launch_bounds__(256) void out_stats_kernel(
    const float* __restrict__ node_data, const float* __restrict__ W_output)
{
    __shared__ float Wsh[16 * 64];
    __shared__ float red[256];
    int tid = threadIdx.x;
    for (int i = tid; i < 1024; i += 256) Wsh[i] = W_output[i];
    __syncthreads();

    int c = tid & 63;
    int r = tid >> 6;  // 0..3
    int n0 = blockIdx.x * 64;
    float lsum = 0.f, lsq = 0.f;
    for (int i = 0; i < 16; i++) {
        int n = n0 + r + i * 4;
        if (n < NN) {
            float zz = g_z[n];
            float inv = zz > 0.f ? 0.25f / zz : 0.f;  // fold /sqrt(16)
            float o = 0.f;
            const float* agg = g_agg + n * 16;
            #pragma unroll
            for (int j = 0; j < 16; j++) o += agg[j] * Wsh[j * 64 + c];
            o = o * inv + node_data[(size_t)n * 64 + c];
            g_outpre[(size_t)n * 64 + c] = o;
            lsum += o;
            lsq += o * o;
        }
    }
    red[tid] = lsum;
    __syncthreads();
    if (r == 0) atomicAdd(&g_colsum[c], red[c] + red[64 + c] + red[128 + c] + red[192 + c]);
    __syncthreads();
    red[tid] = lsq;
    __syncthreads();
    if (r == 0) atomicAdd(&g_colsumsq[c], red[c] + red[64 + c] + red[128 + c] + red[192 + c]);
}

// ---------------- batchnorm finalize ----------------
__global__ void bn_kernel(const float* __restrict__ bnw, const float* __restrict__ bnb,
                          float* __restrict__ out)
{
    int i = blockIdx.x * 256 + threadIdx.x;
    if (i >= NN * 64) return;
    int c = i & 63;
    const float invN = 1.f / NN;
    float mean = g_colsum[c] * invN;
    float var = g_colsumsq[c] * invN - mean * mean;
    out[i] = (g_outpre[i] - mean) * rsqrtf(var + 1e-5f) * bnw[c] + bnb[c];
}

// ---------------- launch ----------------
extern "C" void kernel_launch(void* const* d_in, const int* in_sizes, int n_in,
                              void* d_out, int out_size)
{
    const float* node_data = (const float*)d_in[0];
    const int*   edge_index = (const int*)d_in[1];
    const float* edge_data = (const float*)d_in[2];
    const float* edge_sh   = (const float*)d_in[3];
    const float* W_input = (const float*)d_in[4];
    const float* W_query = (const float*)d_in[5];
    const float* W_dot   = (const float*)d_in[6];
    const float* W_output = (const float*)d_in[7];
    const float* Wk1 = (const float*)d_in[8];
    const float* bk1 = (const float*)d_in[9];
    const float* Wk2 = (const float*)d_in[10];
    const float* bk2 = (const float*)d_in[11];
    const float* Wk3 = (const float*)d_in[12];
    const float* bk3 = (const float*)d_in[13];
    const float* Wv1 = (const float*)d_in[14];
    const float* bv1 = (const float*)d_in[15];
    const float* Wv2 = (const float*)d_in[16];
    const float* bv2 = (const float*)d_in[17];
    const float* Wv3 = (const float*)d_in[18];
    const float* bv3 = (const float*)d_in[19];
    const float* bn_weight = (const float*)d_in[20];
    const float* bn_bias   = (const float*)d_in[21];
    float* out = (float*)d_out;

    void *p_h1k, *p_h2k, *p_h1v, *p_h2v, *p_WK, *p_WV;
    cudaGetSymbolAddress(&p_h1k, g_h1k);
    cudaGetSymbolAddress(&p_h2k, g_h2k);
    cudaGetSymbolAddress(&p_h1v, g_h1v);
    cudaGetSymbolAddress(&p_h2v, g_h2v);
    cudaGetSymbolAddress(&p_WK, g_WK);
    cudaGetSymbolAddress(&p_WV, g_WV);

    init_kernel<<<(NE + 255) / 256, 256>>>();
    node_kernel<<<(NN + 7) / 8, 128>>>(node_data, W_input, W_query, W_dot);

    dim3 g1(1, NE / 128);
    gemm_kernel<true><<<g1, 256>>>(edge_data, Wk1, bk1, (float*)p_h1k, NE, 128, 32);
    gemm_kernel<true><<<g1, 256>>>((const float*)p_h1k, Wk2, bk2, (float*)p_h2k, NE, 128, 128);
    gemm_kernel<true><<<g1, 256>>>(edge_data, Wv1, bv1, (float*)p_h1v, NE, 128, 32);
    gemm_kernel<true><<<g1, 256>>>((const float*)p_h1v, Wv2, bv2, (float*)p_h2v, NE, 128, 128);

    dim3 gk(4, NE / 128);
    gemm_kernel<false><<<gk, 256>>>((const float*)p_h2k, Wk3, bk3, (float*)p_WK, NE, 512, 128);
    dim3 gv(8, NE / 128);
    gemm_kernel<false><<<gv, 256>>>((const float*)p_h2v, Wv3, bv3, (float*)p_WV, NE, 1024, 128);

    uv_kernel<<<NE / 8, 256>>>(edge_index, edge_sh);
    attn_agg_kernel<<<(NE + 255) / 256, 256>>>(edge_index);
    out_stats_kernel<<<(NN + 63) / 64, 256>>>(node_data, W_output);
    bn_kernel<<<(NN * 64 + 255) / 256, 256>>>(bn_weight, bn_bias, out);
}